// round 8
// baseline (speedup 1.0000x reference)
#include <cuda_runtime.h>
#include <cstdint>

#define NB 16
#define TT 128
#define VV 64
#define FF 16
#define TBL 8                    // timesteps per k1 block
#define NTB (TT / TBL)           // 16 t-blocks
#define NK 32                    // k-offsets (pairs (i, i+k), k=1..32)
#define PADF 20                  // padded feature stride (80B, 16B-aligned)

// scratch[slice][n][k-1][i]  (16*16*32*64 floats = 2 MB)
__device__ __align__(16) float g_part[NTB * NB * NK * VV];
// e-scratch[n][k-1][i] (16*32*64 floats = 128 KB)
__device__ __align__(16) float g_e[NB * NK * VV];

// Parity swizzle: even logical rows -> physical 0..31, odd -> 32..63.
__device__ __forceinline__ int prow(int r) {
    r &= 63;
    return (r >> 1) + ((r & 1) << 5);
}

// ---------------------------------------------------------------------------
// Kernel 1 (symmetric, 2-wide i blocking): for k=1..32,
//   partial[tb][n][k-1][i] = sum_{8 t, 16 f} a[f] * |x[t,i,f] - x[t,(i+k)%64,f]|
// ---------------------------------------------------------------------------
__global__ __launch_bounds__(256, 2) void gl_partial_kernel(
    const float* __restrict__ x, const float* __restrict__ a)
{
    __shared__ __align__(16) float tile[TBL][VV][PADF];   // 40 KB

    const int n   = blockIdx.y;
    const int tb  = blockIdx.x;
    const int tid = threadIdx.x;
    const int q    = tid & 127;       // pair-thread id
    const int slot = tid >> 7;        // t-slot 0/1
    const int i0   = (q & 31) * 2;    // even base vertex
    const int k0   = (q >> 5) * 8;    // k-group base (0,8,16,24)

    const float4* src = (const float4*)(x + (size_t)(n * TT + tb * TBL) * VV * FF);
#pragma unroll
    for (int w = tid; w < TBL * VV * 4; w += 256) {
        float4 v = src[w];
        int t  = w >> 8;
        int r  = w & 255;
        int vv = r >> 2;
        int f4 = r & 3;
        *(float4*)&tile[t][prow(vv)][f4 * 4] = v;
    }

    uint64_t af2[8];
#pragma unroll
    for (int k = 0; k < 8; k++) {
        af2[k] = (uint64_t)__float_as_uint(__ldg(&a[2 * k])) |
                 ((uint64_t)__float_as_uint(__ldg(&a[2 * k + 1])) << 32);
    }
    __syncthreads();

    uint64_t acc[2][8];
#pragma unroll
    for (int m = 0; m < 2; m++)
#pragma unroll
        for (int d = 0; d < 8; d++) acc[m][d] = 0ull;

#pragma unroll 1
    for (int tt = 0; tt < 4; tt++) {
        const int t = slot * 4 + tt;
        uint64_t nzi[2][8];
#pragma unroll
        for (int m = 0; m < 2; m++) {
            const ulonglong2* zr =
                (const ulonglong2*)&tile[t][(i0 >> 1) + m * 32][0];
            ulonglong2 z0 = zr[0], z1 = zr[1], z2 = zr[2], z3 = zr[3];
            nzi[m][0] = z0.x ^ 0x8000000080000000ULL;
            nzi[m][1] = z0.y ^ 0x8000000080000000ULL;
            nzi[m][2] = z1.x ^ 0x8000000080000000ULL;
            nzi[m][3] = z1.y ^ 0x8000000080000000ULL;
            nzi[m][4] = z2.x ^ 0x8000000080000000ULL;
            nzi[m][5] = z2.y ^ 0x8000000080000000ULL;
            nzi[m][6] = z3.x ^ 0x8000000080000000ULL;
            nzi[m][7] = z3.y ^ 0x8000000080000000ULL;
        }

#pragma unroll
        for (int r = 1; r <= 9; r++) {
            const ulonglong2* zjr =
                (const ulonglong2*)&tile[t][prow(i0 + k0 + r)][0];
            ulonglong2 w0 = zjr[0], w1 = zjr[1], w2 = zjr[2], w3 = zjr[3];
            uint64_t zj[8] = {w0.x, w0.y, w1.x, w1.y, w2.x, w2.y, w3.x, w3.y};
            if (r <= 8) {
#pragma unroll
                for (int p = 0; p < 8; p++) {
                    uint64_t d;
                    asm("add.rn.f32x2 %0, %1, %2;"
                        : "=l"(d) : "l"(nzi[0][p]), "l"(zj[p]));
                    d &= 0x7FFFFFFF7FFFFFFFULL;
                    asm("fma.rn.f32x2 %0, %1, %2, %3;"
                        : "=l"(acc[0][r - 1]) : "l"(af2[p]), "l"(d), "l"(acc[0][r - 1]));
                }
            }
            if (r >= 2) {
#pragma unroll
                for (int p = 0; p < 8; p++) {
                    uint64_t d;
                    asm("add.rn.f32x2 %0, %1, %2;"
                        : "=l"(d) : "l"(nzi[1][p]), "l"(zj[p]));
                    d &= 0x7FFFFFFF7FFFFFFFULL;
                    asm("fma.rn.f32x2 %0, %1, %2, %3;"
                        : "=l"(acc[1][r - 2]) : "l"(af2[p]), "l"(d), "l"(acc[1][r - 2]));
                }
            }
        }
    }

    float s[2][8];
#pragma unroll
    for (int m = 0; m < 2; m++)
#pragma unroll
        for (int d = 0; d < 8; d++)
            s[m][d] = __uint_as_float((unsigned)acc[m][d]) +
                      __uint_as_float((unsigned)(acc[m][d] >> 32));

    __syncthreads();
    float* red = (float*)tile;
    if (slot == 1) {
#pragma unroll
        for (int m = 0; m < 2; m++)
#pragma unroll
            for (int d = 0; d < 8; d++)
                red[q * 16 + m * 8 + d] = s[m][d];
    }
    __syncthreads();
    if (slot == 0) {
        float* outp = &g_part[(((size_t)tb * NB + n) * NK + k0) * VV + i0];
#pragma unroll
        for (int d = 0; d < 8; d++) {
            float2 w;
            w.x = s[0][d] + red[q * 16 + d];
            w.y = s[1][d] + red[q * 16 + 8 + d];
            *(float2*)(outp + (size_t)d * VV) = w;
        }
    }
}

// ---------------------------------------------------------------------------
// Kernel 2a: slice reduction + exp(relu(mean)) -> g_e[n][k-1][i].
// Grid (8 kg, 16 n), 256 thr. float4 position p = tid>>2 owned by a lane quad;
// lane (tid&3) sums 4 of 16 slices (4 independent LDGs -> guaranteed MLP),
// quad shfl-reduce, leader computes e and stores.
// ---------------------------------------------------------------------------
__global__ __launch_bounds__(256) void gl_reduce_kernel()
{
    const int n   = blockIdx.y;
    const int kg  = blockIdx.x;               // 0..7 (4 k-values each)
    const int tid = threadIdx.x;
    const int p   = tid >> 2;                 // 0..63: local float4 position
    const int sb  = tid & 3;                  // slice sub-group

    const float4* g4 = (const float4*)g_part;
    const int pos = n * (NK * VV / 4) + kg * 64 + p;   // within one slice
    const int sstride = NB * NK * VV / 4;              // 8192 float4 / slice

    float4 v0 = g4[(size_t)(sb + 0)  * sstride + pos];
    float4 v1 = g4[(size_t)(sb + 4)  * sstride + pos];
    float4 v2 = g4[(size_t)(sb + 8)  * sstride + pos];
    float4 v3 = g4[(size_t)(sb + 12) * sstride + pos];
    float4 s;
    s.x = (v0.x + v1.x) + (v2.x + v3.x);
    s.y = (v0.y + v1.y) + (v2.y + v3.y);
    s.z = (v0.z + v1.z) + (v2.z + v3.z);
    s.w = (v0.w + v1.w) + (v2.w + v3.w);

#pragma unroll
    for (int o = 1; o <= 2; o <<= 1) {
        s.x += __shfl_xor_sync(0xffffffffu, s.x, o);
        s.y += __shfl_xor_sync(0xffffffffu, s.y, o);
        s.z += __shfl_xor_sync(0xffffffffu, s.z, o);
        s.w += __shfl_xor_sync(0xffffffffu, s.w, o);
    }

    if (sb == 0) {
        const float inv = 1.0f / (float)TT;
        float4 e;
        e.x = expf(fmaxf(s.x * inv, 0.f));
        e.y = expf(fmaxf(s.y * inv, 0.f));
        e.z = expf(fmaxf(s.z * inv, 0.f));
        e.w = expf(fmaxf(s.w * inv, 0.f));
        ((float4*)g_e)[pos] = e;
    }
}

// ---------------------------------------------------------------------------
// Kernel 2b: per n, load e-values (128KB total, L2-hot), expand to symmetric
// E[64][64], column-normalize over i, write out[n,i,j].
// ---------------------------------------------------------------------------
__global__ __launch_bounds__(512) void gl_finalize_kernel(float* __restrict__ out)
{
    __shared__ float E[VV][VV + 2];
    __shared__ float cinv[VV];

    const int n   = blockIdx.x;
    const int tid = threadIdx.x;

    {   // Phase A: one float4 of e per thread, scatter symmetric.
        float4 e = ((const float4*)g_e)[n * (NK * VV / 4) + tid];
        const int k_act = (tid >> 4) + 1;
        const int i0    = (tid & 15) * 4;
        float ev[4] = {e.x, e.y, e.z, e.w};
#pragma unroll
        for (int pq = 0; pq < 4; pq++) {
            int ii = i0 + pq;
            int jj = (ii + k_act) & 63;
            E[ii][jj] = ev[pq];
            E[jj][ii] = ev[pq];
        }
        if (tid < VV) E[tid][tid] = 1.0f;             // diag: exp(relu(0))
    }
    __syncthreads();

    {   // Phase B: column sums over i (16 warps x 4 columns).
        const int w = tid >> 5, lane = tid & 31;
#pragma unroll
        for (int c = 0; c < 4; c++) {
            int j = w * 4 + c;
            float v = E[lane][j] + E[lane + 32][j];
#pragma unroll
            for (int o = 16; o; o >>= 1) v += __shfl_xor_sync(0xffffffffu, v, o);
            if (lane == 0) cinv[j] = 1.0f / v;
        }
    }
    __syncthreads();

    {   // Phase C: out[n][i][j] = E[i][j] * cinv[j], 2x float4 stores.
        const int i  = tid >> 3;
        const int jb = (tid & 7) * 8;
        float4 w0, w1;
        w0.x = E[i][jb + 0] * cinv[jb + 0];
        w0.y = E[i][jb + 1] * cinv[jb + 1];
        w0.z = E[i][jb + 2] * cinv[jb + 2];
        w0.w = E[i][jb + 3] * cinv[jb + 3];
        w1.x = E[i][jb + 4] * cinv[jb + 4];
        w1.y = E[i][jb + 5] * cinv[jb + 5];
        w1.z = E[i][jb + 6] * cinv[jb + 6];
        w1.w = E[i][jb + 7] * cinv[jb + 7];
        float* o = out + (size_t)n * VV * VV + i * VV + jb;
        *(float4*)o       = w0;
        *(float4*)(o + 4) = w1;
    }
}

extern "C" void kernel_launch(void* const* d_in, const int* in_sizes, int n_in,
                              void* d_out, int out_size)
{
    const float* x = (const float*)d_in[0];       // [16,128,64,16] fp32
    const float* a = (const float*)d_in[1];       // [16,1] fp32
    float* out = (float*)d_out;                   // [16,64,64] fp32

    gl_partial_kernel<<<dim3(NTB, NB), 256>>>(x, a);
    gl_reduce_kernel<<<dim3(8, NB), 256>>>();
    gl_finalize_kernel<<<NB, 512>>>(out);
}